// round 17
// baseline (speedup 1.0000x reference)
#include <cuda_runtime.h>

// 3-level Haar DWT, fully fused — R10 structure (best measured: 35.6us in-kernel,
// DRAM 76.5%) with 128-thread CTAs for finer scheduling granularity.
// x: [B, L=16384] fp32. Output: [cA3 (B*2048) | cD3 (B*2048) | cD2 (B*4096) | cD1 (B*8192)]
//
// One thread per 8 consecutive inputs:
//   loads : 2x LDG.128, default policy (all cache hints measured harmful R11/R12)
//   stores: cD1 STG.128, cD2 STG.64, cD3/cA3 STG.32, default policy — all coalesced.

__global__ __launch_bounds__(128) void haar3_kernel(
    const float4* __restrict__ in4,   // input viewed as float4
    float*  __restrict__ cA3,         // B*2048
    float*  __restrict__ cD3,         // B*2048
    float2* __restrict__ cD2_2,       // B*4096 floats
    float4* __restrict__ cD1_4,       // B*8192 floats
    int total_groups)                 // B * 2048
{
    int t = blockIdx.x * blockDim.x + threadIdx.x;
    if (t >= total_groups) return;

    float4 v0 = in4[2 * t];
    float4 v1 = in4[2 * t + 1];

    const float S  = 0.70710678118654752440f;   // sqrt(1/2)
    const float S2 = 0.5f;                      // S^2
    const float S3 = 0.35355339059327376220f;   // S^3

    // level 1 pair sums/diffs
    float a0 = v0.x + v0.y, d0 = v0.x - v0.y;
    float a1 = v0.z + v0.w, d1 = v0.z - v0.w;
    float a2 = v1.x + v1.y, d2 = v1.x - v1.y;
    float a3 = v1.z + v1.w, d3 = v1.z - v1.w;

    // level 2
    float A0 = a0 + a1, D0 = a0 - a1;
    float A1 = a2 + a3, D1 = a2 - a3;

    // level 3
    float ca3 = S3 * (A0 + A1);
    float cd3 = S3 * (A0 - A1);

    // stores — default caching, all coalesced
    cD1_4[t] = make_float4(S * d0, S * d1, S * d2, S * d3);
    cD2_2[t] = make_float2(S2 * D0, S2 * D1);
    cD3[t]   = cd3;
    cA3[t]   = ca3;
}

extern "C" void kernel_launch(void* const* d_in, const int* in_sizes, int n_in,
                              void* d_out, int out_size)
{
    const float* x = (const float*)d_in[0];
    float* out = (float*)d_out;

    const int L = 16384;
    const int B = in_sizes[0] / L;          // 2048
    const int total_groups = B * (L / 8);   // B * 2048

    // Output layout: [cA3 | cD3 | cD2 | cD1]
    float*  cA3  = out;
    float*  cD3  = out + (size_t)B * (L / 8);                 // + B*2048
    float2* cD2  = (float2*)(out + (size_t)2 * B * (L / 8));  // + B*4096 floats
    float4* cD1  = (float4*)(out + (size_t)B * (L / 2));      // + B*8192 floats

    int threads = 128;
    int blocks = (total_groups + threads - 1) / threads;
    haar3_kernel<<<blocks, threads>>>((const float4*)x, cA3, cD3, cD2, cD1, total_groups);
}